// round 16
// baseline (speedup 1.0000x reference)
#include <cuda_runtime.h>
#include <cstdint>
#include <cstddef>

#define TT   2048
#define DD   1024
#define NTOK 8192      // B*T
#define KVN  48
#define DIN  1408
#define NN   2048      // 2*D
#define NK8  176       // DIN/8

// ---------------- scratch (device globals: allocation-free) ----------------
__device__ float g_blog[NTOK];
__device__ float g_keylog[NTOK * KVN];
__device__ float g_lnh[(size_t)NTOK * DD];
__device__ float g_fa[(size_t)NTOK * DIN];    // film_in in A-fragment order
__device__ float g_bwf[(size_t)NN * DIN];     // film_w tf32, permuted, PAIRED B-frag order
__device__ float g_w2f[64 * 1024];            // [key_w | bound_w | 0] tf32, PAIRED B-frag order

__device__ __forceinline__ float rna_tf32(float x) {
    uint32_t u;
    asm("cvt.rna.tf32.f32 %0, %1;" : "=r"(u) : "f"(x));
    return __uint_as_float(u);
}

__device__ __forceinline__ void cp16(uint32_t dst, const void* src) {
    asm volatile("cp.async.cg.shared.global [%0], [%1], 16;" :: "r"(dst), "l"(src));
}
#define CP_COMMIT() asm volatile("cp.async.commit_group;")
#define CP_WAIT1()  asm volatile("cp.async.wait_group 1;")

#define MMA_TF32(d0,d1,d2,d3,a0,a1,a2,a3,b0,b1)                              \
  asm volatile("mma.sync.aligned.m16n8k8.row.col.f32.tf32.tf32.f32 "         \
    "{%0,%1,%2,%3},{%4,%5,%6,%7},{%8,%9},{%0,%1,%2,%3};\n"                   \
    : "+f"(d0), "+f"(d1), "+f"(d2), "+f"(d3)                                 \
    : "r"(a0), "r"(a1), "r"(a2), "r"(a3), "r"(b0), "r"(b1))

// ---------------- K0: fused weight prep ------------------------------------
// blocks [0, 2816): film_w -> tf32, permuted, PAIRED B-frag superblocks
// blocks [2816, 2880): [key_w | bound_w | 0] -> tf32 PAIRED B-frag (g_w2f)
#define RB_BLOCKS 2816   // (128 * NK8) / 8
__device__ __forceinline__ float w2_at(const float* kw, const float* bw, int k, int n) {
    if (n < KVN) return kw[k * KVN + n];
    if (n == KVN) return bw[k];
    return 0.f;
}
__global__ __launch_bounds__(256) void k_prep(const float* __restrict__ film_w,
                                              const float* __restrict__ key_w,
                                              const float* __restrict__ bound_w) {
    int lane = threadIdx.x & 31;
    if (blockIdx.x < RB_BLOCKS) {
        int w = blockIdx.x * 8 + (threadIdx.x >> 5);   // superblock id = P*NK8 + kt8
        int kt8 = w % NK8, P = w / NK8;                // P < 128
        int prow0 = P * 16 + (lane >> 2);
        int prow1 = prow0 + 8;
        int k = kt8 * 8 + (lane & 3);
        int g20 = prow0 >> 7, r0 = prow0 & 127;
        int n0 = (r0 < 64) ? (g20 * 64 + r0) : (1024 + g20 * 64 + (r0 - 64));
        int g21 = prow1 >> 7, r1 = prow1 & 127;
        int n1 = (r1 < 64) ? (g21 * 64 + r1) : (1024 + g21 * 64 + (r1 - 64));
        float4 o;
        o.x = rna_tf32(film_w[(size_t)k * NN + n0]);
        o.y = rna_tf32(film_w[(size_t)(k + 4) * NN + n0]);
        o.z = rna_tf32(film_w[(size_t)k * NN + n1]);
        o.w = rna_tf32(film_w[(size_t)(k + 4) * NN + n1]);
        *(float4*)&g_bwf[((size_t)w << 7) + (lane << 2)] = o;
    } else {
        int w = (blockIdx.x - RB_BLOCKS) * 8 + (threadIdx.x >> 5);   // 0..511
        int kt8 = w & 127, P = w >> 7;
        int prow0 = P * 16 + (lane >> 2);
        int prow1 = prow0 + 8;
        int k = kt8 * 8 + (lane & 3);
        float4 o;
        o.x = rna_tf32(w2_at(key_w, bound_w, k, prow0));
        o.y = rna_tf32(w2_at(key_w, bound_w, k + 4, prow0));
        o.z = rna_tf32(w2_at(key_w, bound_w, k, prow1));
        o.w = rna_tf32(w2_at(key_w, bound_w, k + 4, prow1));
        *(float4*)&g_w2f[((size_t)w << 7) + (lane << 2)] = o;
    }
}

// ---------------- K1: tensor-core key+boundary logits (proven R13) ---------
#define K1_STG_F 6144
#define K1_SMEM (3 * K1_STG_F * 4)
__global__ __launch_bounds__(256, 1) void k1_tc(const float* __restrict__ h,
                                                const float* __restrict__ key_b,
                                                const float* __restrict__ bound_b) {
    extern __shared__ float sm[];
    uint32_t sb = (uint32_t)__cvta_generic_to_shared(sm);
    int tid = threadIdx.x, warp = tid >> 5, lane = tid & 31;
    int grp = lane >> 2, tig = lane & 3;
    int wm = (warp & 3) * 32, wn = (warp >> 2) * 32;
    int tok0 = blockIdx.x * 128;

    float acc[2][4][4];
#pragma unroll
    for (int i = 0; i < 2; i++)
#pragma unroll
        for (int j = 0; j < 4; j++)
#pragma unroll
            for (int r = 0; r < 4; r++) acc[i][j][r] = 0.f;

    const float* srcA[4];
    uint32_t dstA[4];
#pragma unroll
    for (int p = 0; p < 4; p++) {
        int c = p * 256 + tid;
        int row = c >> 3, kc = c & 7;
        srcA[p] = h + (size_t)(tok0 + row) * DD + kc * 4;
        int swz = (kc * 4) ^ ((row & 7) << 2);
        dstA[p] = row * 128 + swz * 4;
    }
    size_t srcB[2];
    uint32_t dstB[2];
#pragma unroll
    for (int p = 0; p < 2; p++) {
        int c2 = p * 256 + tid;
        int s = c2 >> 5, inner = c2 & 31;
        srcB[p] = (size_t)(s >> 2) * 16384 + (s & 3) * 128 + inner * 4;
        dstB[p] = 16384 + c2 * 16;
    }

    auto load_stage = [&](int s, int kt) {
        uint32_t base = sb + s * (K1_STG_F * 4);
#pragma unroll
        for (int p = 0; p < 4; p++)
            cp16(base + dstA[p], srcA[p] + kt * 32);
#pragma unroll
        for (int p = 0; p < 2; p++)
            cp16(base + dstB[p], g_w2f + srcB[p] + (size_t)kt * 512);
    };

#pragma unroll
    for (int s = 0; s < 2; s++) { load_stage(s, s); CP_COMMIT(); }

    for (int kt = 0; kt < 32; kt++) {
        CP_WAIT1();
        __syncthreads();
        if (kt + 2 < 32) load_stage((kt + 2) % 3, kt + 2);
        CP_COMMIT();
        const float* st = sm + (kt % 3) * K1_STG_F;
#pragma unroll
        for (int kb = 0; kb < 4; kb++) {
            uint32_t af[2][4];
#pragma unroll
            for (int mi = 0; mi < 2; mi++) {
                int r0 = wm + mi * 16 + grp;
                int r1 = r0 + 8;
                int ck = kb * 8 + tig;
                af[mi][0] = __float_as_uint(rna_tf32(st[r0 * 32 + (ck ^ ((r0 & 7) << 2))]));
                af[mi][1] = __float_as_uint(rna_tf32(st[r1 * 32 + (ck ^ ((r1 & 7) << 2))]));
                af[mi][2] = __float_as_uint(rna_tf32(st[r0 * 32 + ((ck + 4) ^ ((r0 & 7) << 2))]));
                af[mi][3] = __float_as_uint(rna_tf32(st[r1 * 32 + ((ck + 4) ^ ((r1 & 7) << 2))]));
            }
            uint4 bq[2];
#pragma unroll
            for (int np = 0; np < 2; np++)
                bq[np] = *(const uint4*)(st + 4096 + ((((wn >> 4) + np) << 2) + kb) * 128 + (lane << 2));
#pragma unroll
            for (int mi = 0; mi < 2; mi++) {
#pragma unroll
                for (int ni = 0; ni < 4; ni++) {
                    uint32_t b0 = (ni & 1) ? bq[ni >> 1].z : bq[ni >> 1].x;
                    uint32_t b1 = (ni & 1) ? bq[ni >> 1].w : bq[ni >> 1].y;
                    MMA_TF32(acc[mi][ni][0], acc[mi][ni][1], acc[mi][ni][2], acc[mi][ni][3],
                             af[mi][0], af[mi][1], af[mi][2], af[mi][3], b0, b1);
                }
            }
        }
    }

    float bb = bound_b[0];
#pragma unroll
    for (int mi = 0; mi < 2; mi++) {
#pragma unroll
        for (int ni = 0; ni < 4; ni++) {
            int cl = wn + ni * 8 + tig * 2;
#pragma unroll
            for (int half = 0; half < 2; half++) {
                int rl = wm + mi * 16 + grp + half * 8;
                int token = tok0 + rl;
                float v0 = acc[mi][ni][half * 2];
                float v1 = acc[mi][ni][half * 2 + 1];
                if (cl < KVN) {
                    float2 o;
                    o.x = v0 + key_b[cl];
                    o.y = v1 + key_b[cl + 1];
                    *(float2*)&g_keylog[(size_t)token * KVN + cl] = o;
                } else if (cl == KVN) {
                    g_blog[token] = v0 + bb;
                }
            }
        }
    }
}

// ---------------- K3: paired-token film prep (tile-per-thread writer) ------
__global__ __launch_bounds__(256) void k_film2(const float* __restrict__ h,
                                               const float* __restrict__ conv_w,
                                               const float* __restrict__ conv_b,
                                               const float* __restrict__ e0,
                                               const float* __restrict__ e1,
                                               const float* __restrict__ key_emb,
                                               const float* __restrict__ ln_in_g,
                                               const float* __restrict__ ln_in_b,
                                               const float* __restrict__ ln_h_g,
                                               const float* __restrict__ ln_h_b) {
    __shared__ float xs[2][DIN];
    __shared__ float kl[2][KVN];
    __shared__ float red[2][16];
    __shared__ float s_bs[2];
    int tid = threadIdx.x;
    int half = tid >> 7;          // 0: token t, 1: token t+8
    int wg = tid & 127;
    int lane = tid & 31;
    int w4 = (tid >> 5) & 3;
    int group = blockIdx.x >> 3;  // 16-token group
    int sub = blockIdx.x & 7;
    int token = group * 16 + sub + half * 8;

#define HBAR() asm volatile("bar.sync %0, 128;" :: "r"(1 + half) : "memory")

    if (wg == 0) {
        int b = token >> 11, t = token & (TT - 1);
        float s = 0.f;
#pragma unroll
        for (int j = 0; j < 9; j++) {
            int tt = t + j - 4;
            if (tt >= 0 && tt < TT) s += conv_w[j] * g_blog[b * TT + tt];
        }
        s += conv_b[0];
        s_bs[half] = 1.f / (1.f + __expf(-s));
    }

    float4 hv0 = *(const float4*)&h[(size_t)token * DD + wg * 8];
    float4 hv1 = *(const float4*)&h[(size_t)token * DD + wg * 8 + 4];
    *(float4*)&xs[half][wg * 8] = hv0;
    *(float4*)&xs[half][wg * 8 + 4] = hv1;
    float ps = hv0.x + hv0.y + hv0.z + hv0.w + hv1.x + hv1.y + hv1.z + hv1.w;
    float pq = hv0.x * hv0.x + hv0.y * hv0.y + hv0.z * hv0.z + hv0.w * hv0.w
             + hv1.x * hv1.x + hv1.y * hv1.y + hv1.z * hv1.z + hv1.w * hv1.w;

    float s = ps, q = pq;
#pragma unroll
    for (int o = 16; o; o >>= 1) {
        s += __shfl_xor_sync(0xffffffffu, s, o);
        q += __shfl_xor_sync(0xffffffffu, q, o);
    }
    if (lane == 0) { red[half][w4] = s; red[half][4 + w4] = q; }
    HBAR();
    if (wg == 0) {
        float S = red[half][0] + red[half][1] + red[half][2] + red[half][3];
        float Q = red[half][4] + red[half][5] + red[half][6] + red[half][7];
        red[half][8] = S; red[half][9] = Q;
    }
    HBAR();
    float muh = red[half][8] * (1.f / DD);
    float varh = red[half][9] * (1.f / DD) - muh * muh;
    float rsh = rsqrtf(varh + 1e-5f);
    {
        float4 g0 = *(const float4*)&ln_h_g[wg * 8];
        float4 g1 = *(const float4*)&ln_h_g[wg * 8 + 4];
        float4 b0 = *(const float4*)&ln_h_b[wg * 8];
        float4 b1 = *(const float4*)&ln_h_b[wg * 8 + 4];
        float4 z0, z1;
        z0.x = (hv0.x - muh) * rsh * g0.x + b0.x;
        z0.y = (hv0.y - muh) * rsh * g0.y + b0.y;
        z0.z = (hv0.z - muh) * rsh * g0.z + b0.z;
        z0.w = (hv0.w - muh) * rsh * g0.w + b0.w;
        z1.x = (hv1.x - muh) * rsh * g1.x + b1.x;
        z1.y = (hv1.y - muh) * rsh * g1.y + b1.y;
        z1.z = (hv1.z - muh) * rsh * g1.z + b1.z;
        z1.w = (hv1.w - muh) * rsh * g1.w + b1.w;
        *(float4*)&g_lnh[(size_t)token * DD + wg * 8] = z0;
        *(float4*)&g_lnh[(size_t)token * DD + wg * 8 + 4] = z1;
    }

    if (wg < KVN) kl[half][wg] = g_keylog[(size_t)token * KVN + wg];
    HBAR();
    if (wg < 32) {
        float m = kl[half][lane];
        if (lane < 16) m = fmaxf(m, kl[half][32 + lane]);
#pragma unroll
        for (int o = 16; o; o >>= 1) m = fmaxf(m, __shfl_xor_sync(0xffffffffu, m, o));
        if (lane == 0) red[half][10] = m;
    }
    HBAR();
    float mx = red[half][10];
    if (wg < KVN) kl[half][wg] = __expf(kl[half][wg] - mx);
    HBAR();
    if (wg < 32) {
        float sm2 = kl[half][lane] + (lane < 16 ? kl[half][32 + lane] : 0.f);
#pragma unroll
        for (int o = 16; o; o >>= 1) sm2 += __shfl_xor_sync(0xffffffffu, sm2, o);
        if (lane == 0) red[half][11] = 1.f / sm2;
    }
    HBAR();
    float sinv = red[half][11];

    float ekv = 0.f;
#pragma unroll
    for (int k = 0; k < KVN; k++) ekv += kl[half][k] * key_emb[k * 128 + wg];
    ekv *= sinv;
    xs[half][1280 + wg] = ekv;
    float bs = s_bs[half];
    float eb0 = bs * e1[wg] + (1.f - bs) * e0[wg];
    float eb1 = bs * e1[128 + wg] + (1.f - bs) * e0[128 + wg];
    xs[half][1024 + wg] = eb0;
    xs[half][1152 + wg] = eb1;

    float ts = eb0 + eb1 + ekv;
    float tq = eb0 * eb0 + eb1 * eb1 + ekv * ekv;
    s = ps + ts; q = pq + tq;
#pragma unroll
    for (int o = 16; o; o >>= 1) {
        s += __shfl_xor_sync(0xffffffffu, s, o);
        q += __shfl_xor_sync(0xffffffffu, q, o);
    }
    if (lane == 0) { red[half][w4] = s; red[half][4 + w4] = q; }
    HBAR();
    if (wg == 0) {
        float S = red[half][0] + red[half][1] + red[half][2] + red[half][3];
        float Q = red[half][4] + red[half][5] + red[half][6] + red[half][7];
        float mu = S * (1.f / DIN);
        float var = Q * (1.f / DIN) - mu * mu;
        red[half][12] = mu;
        red[half][13] = rsqrtf(var + 1e-5f);
    }
    __syncthreads();    // both halves complete; xs[0], xs[1], red valid

    // joint writer: one A-tile (8 dims) per thread, 4 LDS.128 + 4 STG.128
    if (tid < NK8) {
        float muA = red[0][12], rsA = red[0][13];
        float muB = red[1][12], rsB = red[1][13];
        int T = tid;
        float4 x0lo = *(float4*)&xs[0][T * 8];
        float4 x0hi = *(float4*)&xs[0][T * 8 + 4];
        float4 x1lo = *(float4*)&xs[1][T * 8];
        float4 x1hi = *(float4*)&xs[1][T * 8 + 4];
        float4 glo = *(const float4*)&ln_in_g[T * 8];
        float4 ghi = *(const float4*)&ln_in_g[T * 8 + 4];
        float4 blo = *(const float4*)&ln_in_b[T * 8];
        float4 bhi = *(const float4*)&ln_in_b[T * 8 + 4];
        float* dst = &g_fa[(((size_t)group * NK8 + T) << 7) + sub * 16];
        float4 o0, o1, o2, o3;
        o0.x = rna_tf32((x0lo.x - muA) * rsA * glo.x + blo.x);
        o0.y = rna_tf32((x1lo.x - muB) * rsB * glo.x + blo.x);
        o0.z = rna_tf32((x0hi.x - muA) * rsA * ghi.x + bhi.x);
        o0.w = rna_tf32((x1hi.x - muB) * rsB * ghi.x + bhi.x);
        o1.x = rna_tf32((x0lo.y - muA) * rsA * glo.y + blo.y);
        o1.y = rna_tf32((x1lo.y - muB) * rsB * glo.y + blo.y);
        o1.z = rna_tf32((x0hi.y - muA) * rsA * ghi.y + bhi.y);
        o1.w = rna_tf32((x1hi.y - muB) * rsB * ghi.y + bhi.y);
        o2.x = rna_tf32((x0lo.z - muA) * rsA * glo.z + blo.z);
        o2.y = rna_tf32((x1lo.z - muB) * rsB * glo.z + blo.z);
        o2.z = rna_tf32((x0hi.z - muA) * rsA * ghi.z + bhi.z);
        o2.w = rna_tf32((x1hi.z - muB) * rsB * ghi.z + bhi.z);
        o3.x = rna_tf32((x0lo.w - muA) * rsA * glo.w + blo.w);
        o3.y = rna_tf32((x1lo.w - muB) * rsB * glo.w + blo.w);
        o3.z = rna_tf32((x0hi.w - muA) * rsA * ghi.w + bhi.w);
        o3.w = rna_tf32((x1hi.w - muB) * rsB * ghi.w + bhi.w);
        *(float4*)&dst[0]  = o0;
        *(float4*)&dst[4]  = o1;
        *(float4*)&dst[8]  = o2;
        *(float4*)&dst[12] = o3;
    }
#undef HBAR
}

// ---------------- K4: frag-layout tf32 GEMM + balanced window writer -------
#define STG_F 8192                 // floats per stage
#define SMEM_TOTAL_G (3 * STG_F * 4)
__global__ __launch_bounds__(256, 2) void k_gemm8(const float* __restrict__ bias,
                                                  const float* __restrict__ h,
                                                  float* __restrict__ out) {
    extern __shared__ float sm[];
    uint32_t sb = (uint32_t)__cvta_generic_to_shared(sm);
    int tid = threadIdx.x;
    int bx = blockIdx.x;                 // 0..15
    int m0 = blockIdx.y * 128;
    int warp = tid >> 5, lane = tid & 31;
    int wm = (warp & 1) * 64, wn = (warp >> 1) * 32;
    int grp = lane >> 2, tig = lane & 3;

    float acc[4][4][4];
#pragma unroll
    for (int i = 0; i < 4; i++)
#pragma unroll
        for (int j = 0; j < 4; j++)
#pragma unroll
            for (int r = 0; r < 4; r++) acc[i][j][r] = 0.f;

    int aidx[4], soffA[4], bidx[4], soffB[4];
#pragma unroll
    for (int p = 0; p < 4; p++) {
        int lin = p * 256 + tid;
        int tileA = lin >> 5, chA = lin & 31;          // A: 32 tiles x 512B
        aidx[p] = (((m0 >> 4) + (tileA >> 2)) * NK8 + (tileA & 3)) * 128 + chA * 4;
        soffA[p] = tileA * 512 + chA * 16;
        int tileB = lin >> 5, chB = lin & 31;          // B: 32 superblocks x 512B
        bidx[p] = ((bx * 8 + (tileB >> 2)) * NK8 + (tileB & 3)) * 128 + chB * 4;
        soffB[p] = 16384 + tileB * 512 + chB * 16;
    }

    auto load_stage = [&](int s, int kt) {
        uint32_t base = sb + s * (STG_F * 4);
#pragma unroll
        for (int p = 0; p < 4; p++) {
            cp16(base + soffA[p], g_fa  + (size_t)aidx[p] + (size_t)kt * 512);
            cp16(base + soffB[p], g_bwf + (size_t)bidx[p] + (size_t)kt * 512);
        }
    };

#pragma unroll
    for (int s = 0; s < 2; s++) { load_stage(s, s); CP_COMMIT(); }

    for (int kt = 0; kt < 44; kt++) {
        CP_WAIT1();
        __syncthreads();
        if (kt + 2 < 44) load_stage((kt + 2) % 3, kt + 2);
        CP_COMMIT();
        const float* st = sm + (kt % 3) * STG_F;
#pragma unroll
        for (int kb = 0; kb < 4; kb++) {
            uint4 afr[4];
            uint4 bq[2];
#pragma unroll
            for (int mi = 0; mi < 4; mi++)
                afr[mi] = *(const uint4*)(st + ((((wm >> 4) + mi) << 2) + kb) * 128 + (lane << 2));
#pragma unroll
            for (int np = 0; np < 2; np++)
                bq[np] = *(const uint4*)(st + 4096 + ((((wn >> 4) + np) << 2) + kb) * 128 + (lane << 2));
#pragma unroll
            for (int mi = 0; mi < 4; mi++) {
#pragma unroll
                for (int ni = 0; ni < 4; ni++) {
                    uint32_t b0 = (ni & 1) ? bq[ni >> 1].z : bq[ni >> 1].x;
                    uint32_t b1 = (ni & 1) ? bq[ni >> 1].w : bq[ni >> 1].y;
                    MMA_TF32(acc[mi][ni][0], acc[mi][ni][1], acc[mi][ni][2], acc[mi][ni][3],
                             afr[mi].x, afr[mi].y, afr[mi].z, afr[mi].w, b0, b1);
                }
            }
        }
    }

    // ---- epilogue: gamma -> smem, then beta warps build z -> out slot 0 ----
    __syncthreads();
    float* Gs = sm;                         // [128][68]
    if (wn < 64) {
#pragma unroll
        for (int ni = 0; ni < 4; ni++) {
            int cl = wn + ni * 8 + tig * 2;
            int gcol = bx * 64 + cl;
            float bi0 = bias[gcol], bi1 = bias[gcol + 1];
#pragma unroll
            for (int mi = 0; mi < 4; mi++) {
                int rl = wm + mi * 16 + grp;
                Gs[rl * 68 + cl]       = acc[mi][ni][0] + bi0;
                Gs[rl * 68 + cl + 1]   = acc[mi][ni][1] + bi1;
                Gs[(rl + 8) * 68 + cl]     = acc[mi][ni][2] + bi0;
                Gs[(rl + 8) * 68 + cl + 1] = acc[mi][ni][3] + bi1;
            }
        }
    }
    __syncthreads();
    if (wn >= 64) {
#pragma unroll
        for (int ni = 0; ni < 4; ni++) {
            int cb = wn - 64 + ni * 8 + tig * 2;
            int gcol = bx * 64 + cb;
            float bb0 = bias[1024 + gcol], bb1 = bias[1024 + gcol + 1];
#pragma unroll
            for (int mi = 0; mi < 4; mi++) {
#pragma unroll
                for (int half = 0; half < 2; half++) {
                    int rl = wm + mi * 16 + grp + half * 8;
                    int token = m0 + rl;
                    float2 l2 = *(const float2*)&g_lnh[(size_t)token * DD + gcol];
                    float ga0 = Gs[rl * 68 + cb], ga1 = Gs[rl * 68 + cb + 1];
                    float2 z2;
                    z2.x = l2.x * (1.f + ga0) + acc[mi][ni][half * 2]     + bb0;
                    z2.y = l2.y * (1.f + ga1) + acc[mi][ni][half * 2 + 1] + bb1;
                    __stcs((float2*)&out[(size_t)token * 18432 + gcol], z2);
                }
            }
        }
    }

    // ---- balanced fused window writer ------------------------------------
    {
        int bb2 = m0 >> 11;
        {
            int j = bx;                               // 0..15
            for (int r = 0; r < 128; r++) {
                int token = m0 + r;
                int t = token & (TT - 1);
                int srct = min(max(t + j - 8, 0), TT - 1);
                float4 v = *(const float4*)&h[((size_t)(bb2 * TT + srct)) * DD + tid * 4];
                __stcs((float4*)&out[(size_t)token * 18432 + (size_t)(1 + j) * DD + tid * 4], v);
            }
        }
        {
            int r0 = bx * 8;                          // slot 17 share
            for (int r = r0; r < r0 + 8; r++) {
                int token = m0 + r;
                int t = token & (TT - 1);
                int srct = min(t + 8, TT - 1);        // j=16 -> t+8, clamped
                float4 v = *(const float4*)&h[((size_t)(bb2 * TT + srct)) * DD + tid * 4];
                __stcs((float4*)&out[(size_t)token * 18432 + (size_t)17 * DD + tid * 4], v);
            }
        }
    }
}

// ---------------------------------------------------------------------------
extern "C" void kernel_launch(void* const* d_in, const int* in_sizes, int n_in,
                              void* d_out, int out_size) {
    const float* h        = (const float*)d_in[0];
    const float* bound_w  = (const float*)d_in[1];
    const float* bound_b  = (const float*)d_in[2];
    const float* conv_w   = (const float*)d_in[3];
    const float* conv_b   = (const float*)d_in[4];
    const float* e0       = (const float*)d_in[5];
    const float* e1       = (const float*)d_in[6];
    const float* key_emb  = (const float*)d_in[7];
    const float* key_w    = (const float*)d_in[8];
    const float* key_b    = (const float*)d_in[9];
    const float* ln_in_g  = (const float*)d_in[10];
    const float* ln_in_b  = (const float*)d_in[11];
    const float* film_w   = (const float*)d_in[12];
    const float* film_b   = (const float*)d_in[13];
    const float* ln_h_g   = (const float*)d_in[14];
    const float* ln_h_b   = (const float*)d_in[15];
    float* out = (float*)d_out;

    cudaFuncSetAttribute(k_gemm8, cudaFuncAttributeMaxDynamicSharedMemorySize, SMEM_TOTAL_G);
    cudaFuncSetAttribute(k1_tc,   cudaFuncAttributeMaxDynamicSharedMemorySize, K1_SMEM);

    k_prep <<<RB_BLOCKS + 64, 256>>>(film_w, key_w, bound_w);
    k1_tc  <<<NTOK / 128, 256, K1_SMEM>>>(h, key_b, bound_b);
    k_film2<<<NTOK / 2, 256>>>(h, conv_w, conv_b, e0, e1, key_emb, ln_in_g, ln_in_b, ln_h_g, ln_h_b);
    k_gemm8<<<dim3(16, NTOK / 128), 256, SMEM_TOTAL_G>>>(film_b, h, out);
}